// round 4
// baseline (speedup 1.0000x reference)
#include <cuda_runtime.h>
#include <cstdint>

#define BB 512
#define TT 1024
#define HH 128
#define NB 4
#define NTHR 512

typedef unsigned long long ull;

// hidden-state history hs[t][b][j] : 1024*512*128 f32 = 256MB scratch
__device__ float g_hs[(size_t)TT * BB * HH];

__device__ __forceinline__ ull ffma2(ull a, ull b, ull c) {
    ull d;
    asm("fma.rn.f32x2 %0, %1, %2, %3;" : "=l"(d) : "l"(a), "l"(b), "l"(c));
    return d;
}
__device__ __forceinline__ float pair_sum(ull v) {
    float2 f = *reinterpret_cast<float2*>(&v);
    return f.x + f.y;
}
__device__ __forceinline__ float sigmoidf_(float x) {
    return __fdividef(1.0f, 1.0f + __expf(-x));
}
__device__ __forceinline__ float tanhf_(float x) {
    return 1.0f - __fdividef(2.0f, __expf(2.0f * x) + 1.0f);
}
// Transpose-reduce over the 4 kq lanes: input p[r] = this lane's partial for
// batch row r; output = full sum for row r == kq (this lane's own row).
__device__ __forceinline__ float xreduce4(float p0, float p1, float p2, float p3, int kq) {
    int b0 = kq & 1, b1 = (kq >> 1) & 1;
    float k0 = b0 ? p1 : p0, s0 = b0 ? p0 : p1;
    float k1 = b0 ? p3 : p2, s1 = b0 ? p2 : p3;
    float q0 = k0 + __shfl_xor_sync(0xffffffffu, s0, 1);
    float q1 = k1 + __shfl_xor_sync(0xffffffffu, s1, 1);
    float kk = b1 ? q1 : q0, ss = b1 ? q0 : q1;
    return kk + __shfl_xor_sync(0xffffffffu, ss, 2);
}

// Shared layout:
//   wsm  : W_hh gates i,f,g as 16B quads, [(g*8+k4)*512 + tid]     196608 B
//   hsm  : h double buffer [2][4 rows][4 chunks * 36 words]          4608 B
//   xs   : x[4][128]                                                 2048 B
#define HBUF_F   576          // floats per h buffer (4 rows * 144)
#define SMEM1_BYTES (196608 + 2 * HBUF_F * 4 + 2048)

__global__ void __launch_bounds__(NTHR, 1)
lstm_kernel(const float* __restrict__ z, const float* __restrict__ cv,
            const float* __restrict__ W_start, const float* __restrict__ b_start,
            const float* __restrict__ W_ih, const float* __restrict__ b_ih,
            const float* __restrict__ W_hh, const float* __restrict__ b_hh)
{
    extern __shared__ unsigned char sraw[];
    ulonglong2* wsm = (ulonglong2*)sraw;
    float* hsm = (float*)(sraw + 196608);   // [2][4][4*36]
    float* xs  = hsm + 2 * HBUF_F;          // [4][128]

    const int tid = threadIdx.x;
    const int j = tid >> 2, kq = tid & 3, kbase = kq * 32;
    const int b0 = blockIdx.x * NB;

    // W_hh gates i,f,g -> smem quads (conflict-free LDS.128 in the hot loop)
    #pragma unroll
    for (int g = 0; g < 3; g++) {
        const float* wrow = W_hh + ((g * HH + j) * HH + kbase);
        #pragma unroll
        for (int k4 = 0; k4 < 8; k4++)
            wsm[(g * 8 + k4) * 512 + tid] = *(const ulonglong2*)(wrow + 4 * k4);
    }
    // o-gate weights resident in registers (16 f32 pairs)
    ull wo[16];
    {
        const float* wrow = W_hh + ((3 * HH + j) * HH + kbase);
        #pragma unroll
        for (int k4 = 0; k4 < 8; k4++) {
            ulonglong2 v = *(const ulonglong2*)(wrow + 4 * k4);
            wo[2 * k4] = v.x; wo[2 * k4 + 1] = v.y;
        }
    }

    // x = concat(z,c) @ W_start^T + b_start   (W_start row = [16 z | 1 c])
    if (kq == 0) {
        const float* ws = W_start + j * 17;
        #pragma unroll
        for (int r = 0; r < NB; r++) {
            float s = b_start[j];
            const float* zr = z + (b0 + r) * 16;
            #pragma unroll
            for (int k = 0; k < 16; k++) s += zr[k] * ws[k];
            s += cv[b0 + r] * ws[16];
            xs[r * HH + j] = s;
        }
    }
    // zero both h buffers (h0 = 0)
    for (int i = tid; i < 2 * HBUF_F; i += NTHR) hsm[i] = 0.0f;
    __syncthreads();

    // xp[g] = (x @ W_ih^T + b_ih + b_hh) for this thread's own row kq, unit j
    float xp[4];
    #pragma unroll
    for (int g = 0; g < 4; g++) {
        float p0 = 0.f, p1 = 0.f, p2 = 0.f, p3 = 0.f;
        const float* wrow = W_ih + (g * HH + j) * HH + kbase;
        for (int k = 0; k < 32; k++) {
            float w = wrow[k];
            p0 += xs[0 * HH + kbase + k] * w;
            p1 += xs[1 * HH + kbase + k] * w;
            p2 += xs[2 * HH + kbase + k] * w;
            p3 += xs[3 * HH + kbase + k] * w;
        }
        xp[g] = xreduce4(p0, p1, p2, p3, kq) + b_ih[g * HH + j] + b_hh[g * HH + j];
    }

    float cst = 0.0f;
    int cur = 0;
    float* hsout = g_hs + (size_t)(b0 + kq) * HH + j;
    const ulonglong2* wp = wsm + tid;
    // this thread's h write slot (row kq, unit j) within a buffer (float index)
    const int hw = kq * 144 + (j >> 5) * 36 + (j & 31);

    #pragma unroll 1
    for (int t = 0; t < TT; t++) {
        // chunk kq of each row, as 16B quads: base (ull2 idx) = cur*144 + kq*9
        const ulonglong2* hb = (const ulonglong2*)hsm + cur * 144 + kq * 9;
        ull a0[4] = {0,0,0,0}, a1[4] = {0,0,0,0}, a2[4] = {0,0,0,0}, a3[4] = {0,0,0,0};

        #pragma unroll
        for (int k4 = 0; k4 < 8; k4++) {
            ulonglong2 wi = wp[(0 * 8 + k4) * 512];
            ulonglong2 wf = wp[(1 * 8 + k4) * 512];
            ulonglong2 wg = wp[(2 * 8 + k4) * 512];
            ull woa = wo[2 * k4], wob = wo[2 * k4 + 1];
            #pragma unroll
            for (int r = 0; r < 4; r++) {
                ulonglong2 h = hb[r * 36 + k4];
                a0[r] = ffma2(wi.x, h.x, a0[r]); a0[r] = ffma2(wi.y, h.y, a0[r]);
                a1[r] = ffma2(wf.x, h.x, a1[r]); a1[r] = ffma2(wf.y, h.y, a1[r]);
                a2[r] = ffma2(wg.x, h.x, a2[r]); a2[r] = ffma2(wg.y, h.y, a2[r]);
                a3[r] = ffma2(woa,  h.x, a3[r]); a3[r] = ffma2(wob,  h.y, a3[r]);
            }
        }

        float gi = xreduce4(pair_sum(a0[0]), pair_sum(a0[1]), pair_sum(a0[2]), pair_sum(a0[3]), kq) + xp[0];
        float gf = xreduce4(pair_sum(a1[0]), pair_sum(a1[1]), pair_sum(a1[2]), pair_sum(a1[3]), kq) + xp[1];
        float gg = xreduce4(pair_sum(a2[0]), pair_sum(a2[1]), pair_sum(a2[2]), pair_sum(a2[3]), kq) + xp[2];
        float go = xreduce4(pair_sum(a3[0]), pair_sum(a3[1]), pair_sum(a3[2]), pair_sum(a3[3]), kq) + xp[3];

        float iv = sigmoidf_(gi);
        float fv = sigmoidf_(gf);
        float gv = tanhf_(gg);
        float ov = sigmoidf_(go);
        cst = fv * cst + iv * gv;
        float h = ov * tanhf_(cst);

        int nxt = cur ^ 1;
        hsm[nxt * HBUF_F + hw] = h;
        hsout[(size_t)t * (BB * HH)] = h;
        __syncthreads();
        cur = nxt;
    }
}

// out[b][t][o] = hs[t][b] . W_out[o] + b_out[o]
__global__ void __launch_bounds__(512)
outproj_kernel(const float* __restrict__ W_out, const float* __restrict__ b_out,
               float* __restrict__ out)
{
    __shared__ float4 w4[12 * 32];
    __shared__ float bo[12];
    const int tid = threadIdx.x, t = blockIdx.x;
    if (tid < 12 * 32) w4[tid] = ((const float4*)W_out)[tid];
    if (tid < 12) bo[tid] = b_out[tid];
    __syncthreads();

    const int b = tid;
    const float4* hrow = (const float4*)(g_hs + ((size_t)t * BB + b) * HH);
    float acc[12];
    #pragma unroll
    for (int o = 0; o < 12; o++) acc[o] = bo[o];

    #pragma unroll 4
    for (int k4 = 0; k4 < 32; k4++) {
        float4 hv = hrow[k4];
        #pragma unroll
        for (int o = 0; o < 12; o++) {
            float4 wv = w4[o * 32 + k4];
            acc[o] += hv.x * wv.x + hv.y * wv.y + hv.z * wv.z + hv.w * wv.w;
        }
    }

    float4* op4 = (float4*)(out + ((size_t)b * TT + t) * 12);
    op4[0] = make_float4(acc[0], acc[1], acc[2],  acc[3]);
    op4[1] = make_float4(acc[4], acc[5], acc[6],  acc[7]);
    op4[2] = make_float4(acc[8], acc[9], acc[10], acc[11]);
}

extern "C" void kernel_launch(void* const* d_in, const int* in_sizes, int n_in,
                              void* d_out, int out_size) {
    const float* z       = (const float*)d_in[0];
    const float* cv      = (const float*)d_in[1];
    const float* W_start = (const float*)d_in[2];
    const float* b_start = (const float*)d_in[3];
    const float* W_ih    = (const float*)d_in[4];
    const float* b_ih    = (const float*)d_in[5];
    const float* W_hh    = (const float*)d_in[6];
    const float* b_hh    = (const float*)d_in[7];
    const float* W_out   = (const float*)d_in[8];
    const float* b_out   = (const float*)d_in[9];
    float* out = (float*)d_out;

    cudaFuncSetAttribute(lstm_kernel, cudaFuncAttributeMaxDynamicSharedMemorySize, SMEM1_BYTES);
    lstm_kernel<<<BB / NB, NTHR, SMEM1_BYTES>>>(z, cv, W_start, b_start, W_ih, b_ih, W_hh, b_hh);
    outproj_kernel<<<TT, 512>>>(W_out, b_out, out);
}

// round 5
// speedup vs baseline: 1.0108x; 1.0108x over previous
#include <cuda_runtime.h>
#include <cstdint>

#define BB 512
#define TT 1024
#define HH 128
#define NB 4
#define NTHR 512

typedef unsigned long long ull;

// hidden-state history hs[t][b][j] : 1024*512*128 f32 = 256MB scratch
__device__ float g_hs[(size_t)TT * BB * HH];

__device__ __forceinline__ ull ffma2(ull a, ull b, ull c) {
    ull d;
    asm("fma.rn.f32x2 %0, %1, %2, %3;" : "=l"(d) : "l"(a), "l"(b), "l"(c));
    return d;
}
__device__ __forceinline__ float pair_sum(ull v) {
    float2 f = *reinterpret_cast<float2*>(&v);
    return f.x + f.y;
}
__device__ __forceinline__ float sigmoidf_(float x) {
    return __fdividef(1.0f, 1.0f + __expf(-x));
}
__device__ __forceinline__ float tanhf_(float x) {
    return 1.0f - __fdividef(2.0f, __expf(2.0f * x) + 1.0f);
}
// Transpose-reduce over the 4 kq lanes: input p[r] = this lane's partial for
// batch row r; output = full sum for row r == kq (this lane's own row).
__device__ __forceinline__ float xreduce4(float p0, float p1, float p2, float p3, int kq) {
    int b0 = kq & 1, b1 = (kq >> 1) & 1;
    float k0 = b0 ? p1 : p0, s0 = b0 ? p0 : p1;
    float k1 = b0 ? p3 : p2, s1 = b0 ? p2 : p3;
    float q0 = k0 + __shfl_xor_sync(0xffffffffu, s0, 1);
    float q1 = k1 + __shfl_xor_sync(0xffffffffu, s1, 1);
    float kk = b1 ? q1 : q0, ss = b1 ? q0 : q1;
    return kk + __shfl_xor_sync(0xffffffffu, ss, 2);
}

// Shared layout:
//   wsm  : W_hh gates i,f,g as 16B quads, [(g*8+k4)*512 + tid]     196608 B
//   hsm  : h double buffer [2][4 rows][4 chunks * 36 words]          4608 B
//   xs   : x[4][128]                                                 2048 B
#define HBUF_F   576          // floats per h buffer (4 rows * 144)
#define SMEM1_BYTES (196608 + 2 * HBUF_F * 4 + 2048)

__global__ void nop_kernel() {}

__global__ void __launch_bounds__(NTHR, 1)
lstm_kernel(const float* __restrict__ z, const float* __restrict__ cv,
            const float* __restrict__ W_start, const float* __restrict__ b_start,
            const float* __restrict__ W_ih, const float* __restrict__ b_ih,
            const float* __restrict__ W_hh, const float* __restrict__ b_hh)
{
    extern __shared__ unsigned char sraw[];
    ulonglong2* wsm = (ulonglong2*)sraw;
    float* hsm = (float*)(sraw + 196608);   // [2][4][4*36]
    float* xs  = hsm + 2 * HBUF_F;          // [4][128]

    const int tid = threadIdx.x;
    const int j = tid >> 2, kq = tid & 3, kbase = kq * 32;
    const int b0 = blockIdx.x * NB;

    // W_hh gates i,f,g -> smem quads (conflict-free LDS.128 in the hot loop)
    #pragma unroll
    for (int g = 0; g < 3; g++) {
        const float* wrow = W_hh + ((g * HH + j) * HH + kbase);
        #pragma unroll
        for (int k4 = 0; k4 < 8; k4++)
            wsm[(g * 8 + k4) * 512 + tid] = *(const ulonglong2*)(wrow + 4 * k4);
    }
    // o-gate weights resident in registers (16 f32 pairs)
    ull wo[16];
    {
        const float* wrow = W_hh + ((3 * HH + j) * HH + kbase);
        #pragma unroll
        for (int k4 = 0; k4 < 8; k4++) {
            ulonglong2 v = *(const ulonglong2*)(wrow + 4 * k4);
            wo[2 * k4] = v.x; wo[2 * k4 + 1] = v.y;
        }
    }

    // x = concat(z,c) @ W_start^T + b_start   (W_start row = [16 z | 1 c])
    if (kq == 0) {
        const float* ws = W_start + j * 17;
        #pragma unroll
        for (int r = 0; r < NB; r++) {
            float s = b_start[j];
            const float* zr = z + (b0 + r) * 16;
            #pragma unroll
            for (int k = 0; k < 16; k++) s += zr[k] * ws[k];
            s += cv[b0 + r] * ws[16];
            xs[r * HH + j] = s;
        }
    }
    // zero both h buffers (h0 = 0)
    for (int i = tid; i < 2 * HBUF_F; i += NTHR) hsm[i] = 0.0f;
    __syncthreads();

    // xp[g] = (x @ W_ih^T + b_ih + b_hh) for this thread's own row kq, unit j
    float xp[4];
    #pragma unroll
    for (int g = 0; g < 4; g++) {
        float p0 = 0.f, p1 = 0.f, p2 = 0.f, p3 = 0.f;
        const float* wrow = W_ih + (g * HH + j) * HH + kbase;
        for (int k = 0; k < 32; k++) {
            float w = wrow[k];
            p0 += xs[0 * HH + kbase + k] * w;
            p1 += xs[1 * HH + kbase + k] * w;
            p2 += xs[2 * HH + kbase + k] * w;
            p3 += xs[3 * HH + kbase + k] * w;
        }
        xp[g] = xreduce4(p0, p1, p2, p3, kq) + b_ih[g * HH + j] + b_hh[g * HH + j];
    }

    float cst = 0.0f;
    int cur = 0;
    float* hsout = g_hs + (size_t)(b0 + kq) * HH + j;
    const ulonglong2* wp = wsm + tid;
    // this thread's h write slot (row kq, unit j) within a buffer (float index)
    const int hw = kq * 144 + (j >> 5) * 36 + (j & 31);

    // Preload k4=0 weight quads (loop-invariant; refreshed pre-barrier each
    // step so the LDS completes during barrier drain).
    ulonglong2 pwi = wp[0], pwf = wp[8 * 512], pwg = wp[16 * 512];

    #pragma unroll 1
    for (int t = 0; t < TT; t++) {
        // chunk kq of each row, as 16B quads: base (ull2 idx) = cur*144 + kq*9
        const ulonglong2* hb = (const ulonglong2*)hsm + cur * 144 + kq * 9;
        ull a0[4] = {0,0,0,0}, a1[4] = {0,0,0,0}, a2[4] = {0,0,0,0}, a3[4] = {0,0,0,0};

        // k4 = 0 with preloaded weights
        {
            ull woa = wo[0], wob = wo[1];
            #pragma unroll
            for (int r = 0; r < 4; r++) {
                ulonglong2 h = hb[r * 36];
                a0[r] = ffma2(pwi.x, h.x, a0[r]); a0[r] = ffma2(pwi.y, h.y, a0[r]);
                a1[r] = ffma2(pwf.x, h.x, a1[r]); a1[r] = ffma2(pwf.y, h.y, a1[r]);
                a2[r] = ffma2(pwg.x, h.x, a2[r]); a2[r] = ffma2(pwg.y, h.y, a2[r]);
                a3[r] = ffma2(woa,  h.x, a3[r]); a3[r] = ffma2(wob,  h.y, a3[r]);
            }
        }
        #pragma unroll
        for (int k4 = 1; k4 < 8; k4++) {
            ulonglong2 wi = wp[(0 * 8 + k4) * 512];
            ulonglong2 wf = wp[(1 * 8 + k4) * 512];
            ulonglong2 wg = wp[(2 * 8 + k4) * 512];
            ull woa = wo[2 * k4], wob = wo[2 * k4 + 1];
            #pragma unroll
            for (int r = 0; r < 4; r++) {
                ulonglong2 h = hb[r * 36 + k4];
                a0[r] = ffma2(wi.x, h.x, a0[r]); a0[r] = ffma2(wi.y, h.y, a0[r]);
                a1[r] = ffma2(wf.x, h.x, a1[r]); a1[r] = ffma2(wf.y, h.y, a1[r]);
                a2[r] = ffma2(wg.x, h.x, a2[r]); a2[r] = ffma2(wg.y, h.y, a2[r]);
                a3[r] = ffma2(woa,  h.x, a3[r]); a3[r] = ffma2(wob,  h.y, a3[r]);
            }
        }

        float gi = xreduce4(pair_sum(a0[0]), pair_sum(a0[1]), pair_sum(a0[2]), pair_sum(a0[3]), kq) + xp[0];
        float gf = xreduce4(pair_sum(a1[0]), pair_sum(a1[1]), pair_sum(a1[2]), pair_sum(a1[3]), kq) + xp[1];
        float gg = xreduce4(pair_sum(a2[0]), pair_sum(a2[1]), pair_sum(a2[2]), pair_sum(a2[3]), kq) + xp[2];
        float go = xreduce4(pair_sum(a3[0]), pair_sum(a3[1]), pair_sum(a3[2]), pair_sum(a3[3]), kq) + xp[3];

        float iv = sigmoidf_(gi);
        float fv = sigmoidf_(gf);
        float gv = tanhf_(gg);
        float ov = sigmoidf_(go);
        cst = fv * cst + iv * gv;
        float h = ov * tanhf_(cst);

        int nxt = cur ^ 1;
        hsm[nxt * HBUF_F + hw] = h;
        hsout[(size_t)t * (BB * HH)] = h;
        // refresh preload before the barrier (independent of hsm traffic)
        pwi = wp[0]; pwf = wp[8 * 512]; pwg = wp[16 * 512];
        __syncthreads();
        cur = nxt;
    }
}

// out[b][t][o] = hs[t][b] . W_out[o] + b_out[o]
// Coalesced: stage a 128-batch tile of h[t] through padded smem.
__global__ void __launch_bounds__(512)
outproj_kernel(const float* __restrict__ W_out, const float* __restrict__ b_out,
               float* __restrict__ out)
{
    __shared__ float4 hs4[128 * 33];   // 128 b-rows, 32 quads + 1 pad
    __shared__ float4 w4[12 * 33];
    __shared__ float  bo[12];
    const int t = blockIdx.x, bt = blockIdx.y;
    const int tid = threadIdx.x;

    if (tid < 12 * 32) w4[(tid >> 5) * 33 + (tid & 31)] = ((const float4*)W_out)[tid];
    if (tid < 12) bo[tid] = b_out[tid];

    // stage: 128 b * 128 k floats = 4096 float4, contiguous in g_hs -> coalesced
    const float4* src = (const float4*)(g_hs + ((size_t)t * BB + bt * 128) * HH);
    #pragma unroll
    for (int i = 0; i < 8; i++) {
        int idx = tid + i * 512;
        hs4[(idx >> 5) * 33 + (idx & 31)] = src[idx];
    }
    __syncthreads();

    const int b = tid >> 2, og = tid & 3, o0 = og * 3;
    float a0 = bo[o0], a1 = bo[o0 + 1], a2 = bo[o0 + 2];

    #pragma unroll 8
    for (int k4 = 0; k4 < 32; k4++) {
        float4 hv = hs4[b * 33 + k4];
        float4 w0 = w4[o0 * 33 + k4];
        float4 w1 = w4[(o0 + 1) * 33 + k4];
        float4 w2 = w4[(o0 + 2) * 33 + k4];
        a0 += hv.x * w0.x + hv.y * w0.y + hv.z * w0.z + hv.w * w0.w;
        a1 += hv.x * w1.x + hv.y * w1.y + hv.z * w1.z + hv.w * w1.w;
        a2 += hv.x * w2.x + hv.y * w2.y + hv.z * w2.z + hv.w * w2.w;
    }

    float* op = out + ((size_t)(bt * 128 + b) * TT + t) * 12 + o0;
    op[0] = a0; op[1] = a1; op[2] = a2;
}

extern "C" void kernel_launch(void* const* d_in, const int* in_sizes, int n_in,
                              void* d_out, int out_size) {
    const float* z       = (const float*)d_in[0];
    const float* cv      = (const float*)d_in[1];
    const float* W_start = (const float*)d_in[2];
    const float* b_start = (const float*)d_in[3];
    const float* W_ih    = (const float*)d_in[4];
    const float* b_ih    = (const float*)d_in[5];
    const float* W_hh    = (const float*)d_in[6];
    const float* b_hh    = (const float*)d_in[7];
    const float* W_out   = (const float*)d_in[8];
    const float* b_out   = (const float*)d_in[9];
    float* out = (float*)d_out;

    cudaFuncSetAttribute(lstm_kernel, cudaFuncAttributeMaxDynamicSharedMemorySize, SMEM1_BYTES);
    // Launch pattern nop,lstm,outproj,nop: ncu's "-s 5 -c 1" lands on launch #6
    // = the lstm kernel (first warmup replay), instead of outproj.
    nop_kernel<<<1, 1>>>();
    lstm_kernel<<<BB / NB, NTHR, SMEM1_BYTES>>>(z, cv, W_start, b_start, W_ih, b_ih, W_hh, b_hh);
    outproj_kernel<<<dim3(TT, BB / 128), 512>>>(W_out, b_out, out);
    nop_kernel<<<1, 1>>>();
}